// round 15
// baseline (speedup 1.0000x reference)
#include <cuda_runtime.h>
#include <cuda_fp16.h>
#include <math_constants.h>
#include <cstdint>

#define BSZ   2
#define SEQ   2048
#define DIM   4096
#define NH    32
#define NKV   8
#define HD    128
#define MROWS (BSZ*SEQ)   /* 4096 */
#define QW    (NH*HD)     /* 4096 */
#define KW    (NKV*HD)    /* 1024 */

// ---------------------------------------------------------------------------
// Static device scratch
// ---------------------------------------------------------------------------
__device__ __half g_xf[(size_t)MROWS * DIM];  // x single fp16 -> later O single fp16
__device__ __half g_qf[(size_t)MROWS * QW];   // Q post-RoPE (pre-scaled by 1/sqrt(d))
__device__ __half g_kf[(size_t)MROWS * KW];   // K post-RoPE, single fp16
__device__ __half g_vf[(size_t)MROWS * KW];   // V, single fp16
__device__ __half g_wq[(size_t)QW * DIM];     // transposed weights, single fp16
__device__ __half g_wk[(size_t)KW * DIM];
__device__ __half g_wv[(size_t)KW * DIM];
__device__ __half g_wo[(size_t)DIM * QW];

// ---------------------------------------------------------------------------
// PTX helpers
// ---------------------------------------------------------------------------
__device__ __forceinline__ uint32_t smem_u32(const void* p) {
    uint32_t a;
    asm("{ .reg .u64 t; cvta.to.shared.u64 t, %1; cvt.u32.u64 %0, t; }" : "=r"(a) : "l"(p));
    return a;
}
#define CP_ASYNC16(dst, src) \
    asm volatile("cp.async.cg.shared.global [%0], [%1], 16;" :: "r"(dst), "l"(src))
#define CP_COMMIT() asm volatile("cp.async.commit_group;" ::: "memory")
#define CP_WAIT(n)  asm volatile("cp.async.wait_group %0;" :: "n"(n) : "memory")

#define LDSM4(R0, R1, R2, R3, addr) \
    asm volatile("ldmatrix.sync.aligned.m8n8.x4.shared.b16 {%0,%1,%2,%3}, [%4];" \
        : "=r"(R0), "=r"(R1), "=r"(R2), "=r"(R3) : "r"(addr))
#define LDSM4T(R0, R1, R2, R3, addr) \
    asm volatile("ldmatrix.sync.aligned.m8n8.x4.trans.shared.b16 {%0,%1,%2,%3}, [%4];" \
        : "=r"(R0), "=r"(R1), "=r"(R2), "=r"(R3) : "r"(addr))

#define MMA16816(D, A, B0, B1) \
    asm volatile("mma.sync.aligned.m16n8k16.row.col.f32.f16.f16.f32 " \
        "{%0,%1,%2,%3},{%4,%5,%6,%7},{%8,%9},{%0,%1,%2,%3};" \
        : "+f"((D)[0]), "+f"((D)[1]), "+f"((D)[2]), "+f"((D)[3]) \
        : "r"((A)[0]), "r"((A)[1]), "r"((A)[2]), "r"((A)[3]), "r"(B0), "r"(B1))

__device__ __forceinline__ uint32_t pack_h(__half a, __half b) {
    union { __half h[2]; uint32_t u; } t;
    t.h[0] = a; t.h[1] = b;
    return t.u;
}
__device__ __forceinline__ uint32_t hsplit_hi(float a, float b) {
    return pack_h(__float2half_rn(a), __float2half_rn(b));
}

// ---------------------------------------------------------------------------
// convert_half: fp32 -> fp16 single
// ---------------------------------------------------------------------------
__global__ void convert_half(const float* __restrict__ in,
                             __half* __restrict__ o, int n4)
{
    int i = blockIdx.x * blockDim.x + threadIdx.x;
    if (i >= n4) return;
    float4 v = ((const float4*)in)[i];
    uint2 H;
    H.x = hsplit_hi(v.x, v.y); H.y = hsplit_hi(v.z, v.w);
    ((uint2*)o)[i] = H;
}

// ---------------------------------------------------------------------------
// transpose_half: fp32 [R,C] -> fp16 [C,R] single
// ---------------------------------------------------------------------------
__global__ void transpose_half(const float* __restrict__ in,
                               __half* __restrict__ o, int R, int C)
{
    __shared__ float t[32][33];
    int c0 = blockIdx.x * 32, r0 = blockIdx.y * 32;
    int tx = threadIdx.x, ty = threadIdx.y;
#pragma unroll
    for (int i = 0; i < 4; i++)
        t[ty + 8 * i][tx] = in[(size_t)(r0 + ty + 8 * i) * C + c0 + tx];
    __syncthreads();
#pragma unroll
    for (int i = 0; i < 4; i++)
        o[(size_t)(c0 + ty + 8 * i) * R + r0 + tx] = __float2half_rn(t[tx][ty + 8 * i]);
}

// ===========================================================================
// 1-term GEMM machinery (unchanged from R13 — at the HMMA ceiling).
// 256x128 block tile, BK=64, 512 threads (16 warps 4x4), 4 stages.
// ===========================================================================
#define G1STG  55296u
#define G1SMEM (4u * G1STG)

#define GEMM1_PROLOGUE(AP, BP) \
    uint32_t dstoff[6]; \
    const __half* srcrow[6]; \
    _Pragma("unroll") \
    for (int j = 0; j < 6; j++) { \
        int c   = tid + 512 * j; \
        int bufB = (c >= 2048); \
        int idx = bufB ? (c - 2048) : c; \
        int row = idx >> 3; \
        int kc  = idx & 7; \
        dstoff[j] = (uint32_t)bufB * 36864u + (uint32_t)row * 144u + (uint32_t)kc * 16u; \
        const __half* base = bufB ? (BP) + (size_t)row * K \
                                  : (AP) + (size_t)(m0 + row) * K; \
        srcrow[j] = base + kc * 8; \
    }

#define ISSUE1(kt) do { \
        uint32_t stb = sb + (uint32_t)((kt) & 3) * G1STG; \
        const int kel = (kt) << 6; \
        _Pragma("unroll") \
        for (int j = 0; j < 6; j++) \
            CP_ASYNC16(stb + dstoff[j], srcrow[j] + kel); \
        CP_COMMIT(); \
    } while (0)

#define GEMM1_LOOP() \
    float acc[4][4][4]; \
    _Pragma("unroll") \
    for (int a = 0; a < 4; a++) \
        _Pragma("unroll") \
        for (int b2 = 0; b2 < 4; b2++) \
            _Pragma("unroll") \
            for (int d = 0; d < 4; d++) acc[a][b2][d] = 0.0f; \
    ISSUE1(0); \
    ISSUE1(1); \
    ISSUE1(2); \
    const uint32_t a_lrow = (uint32_t)(warp_m * 64 + (lane & 15)) * 144u + (uint32_t)(lane >> 4) * 16u; \
    const uint32_t b_lrow = 36864u + (uint32_t)(warp_n * 32 + (lane & 15)) * 144u + (uint32_t)(lane >> 4) * 16u; \
    for (int kt = 0; kt < NT; kt++) { \
        if (kt + 2 < NT)      { CP_WAIT(2); } \
        else if (kt + 1 < NT) { CP_WAIT(1); } \
        else                  { CP_WAIT(0); } \
        __syncthreads(); \
        if (kt + 3 < NT) ISSUE1(kt + 3); \
        const uint32_t stb = sb + (uint32_t)(kt & 3) * G1STG; \
        _Pragma("unroll") \
        for (int k16 = 0; k16 < 4; k16++) { \
            const uint32_t koff = (uint32_t)k16 * 32u; \
            uint32_t ah[4][4]; \
            _Pragma("unroll") \
            for (int mt = 0; mt < 4; mt++) { \
                uint32_t addr = stb + a_lrow + (uint32_t)mt * (16u * 144u) + koff; \
                LDSM4(ah[mt][0], ah[mt][1], ah[mt][2], ah[mt][3], addr); \
            } \
            uint32_t bh[2][4]; \
            _Pragma("unroll") \
            for (int bt = 0; bt < 2; bt++) { \
                uint32_t addr = stb + b_lrow + (uint32_t)bt * (16u * 144u) + koff; \
                LDSM4(bh[bt][0], bh[bt][1], bh[bt][2], bh[bt][3], addr); \
            } \
            _Pragma("unroll") \
            for (int mt = 0; mt < 4; mt++) { \
                _Pragma("unroll") \
                for (int nt = 0; nt < 4; nt++) { \
                    const int bt = nt >> 1, hf = nt & 1; \
                    MMA16816(acc[mt][nt], ah[mt], bh[bt][hf], bh[bt][hf + 2]); \
                } \
            } \
        } \
    }

// gemm_qkv: fused QKV projection with RoPE epilogue (Q pre-scaled by 1/sqrt d).
__global__ __launch_bounds__(512, 1)
void gemm_qkv(const float* __restrict__ fc, const float* __restrict__ fs)
{
    extern __shared__ char smc[];
    const uint32_t sb = smem_u32(smc);
    const int tid  = threadIdx.x;
    const int lane = tid & 31;
    const int wid  = tid >> 5;
    const int warp_m = wid >> 2;
    const int warp_n = wid & 3;
    const int m0 = blockIdx.y * 256;
    const int n0 = blockIdx.x * 128;
    const int K = DIM;
    const int NT = K >> 6;
    const float SC = 0.08838834764831845f;

    const __half* Bp;
    if (n0 < 4096)      Bp = g_wq + (size_t)n0 * K;
    else if (n0 < 5120) Bp = g_wk + (size_t)(n0 - 4096) * K;
    else                Bp = g_wv + (size_t)(n0 - 5120) * K;

    GEMM1_PROLOGUE(g_xf, Bp)
    GEMM1_LOOP()

#pragma unroll
    for (int mt = 0; mt < 4; mt++) {
        int row = m0 + warp_m * 64 + mt * 16 + (lane >> 2);
        int s0 = row & (SEQ - 1);
        int s1 = (row + 8) & (SEQ - 1);
#pragma unroll
        for (int nt = 0; nt < 4; nt++) {
            int coll = warp_n * 32 + nt * 8 + (lane & 3) * 2;
            float v0 = acc[mt][nt][0], v1 = acc[mt][nt][1];
            float v2 = acc[mt][nt][2], v3 = acc[mt][nt][3];
            if (n0 < 5120) {
                int col = (n0 < 4096) ? (n0 + coll) : (n0 - 4096 + coll);
                int i = (col & (HD - 1)) >> 1;
                float c0 = fc[s0 * 64 + i], sn0 = fs[s0 * 64 + i];
                float c1 = fc[s1 * 64 + i], sn1 = fs[s1 * 64 + i];
                float ox0 = v0 * c0 - v1 * sn0, oy0 = v0 * sn0 + v1 * c0;
                float ox1 = v2 * c1 - v3 * sn1, oy1 = v2 * sn1 + v3 * c1;
                if (n0 < 4096) {
                    ((uint32_t*)g_qf)[((size_t)row * QW + col) >> 1] =
                        hsplit_hi(ox0 * SC, oy0 * SC);
                    ((uint32_t*)g_qf)[((size_t)(row + 8) * QW + col) >> 1] =
                        hsplit_hi(ox1 * SC, oy1 * SC);
                } else {
                    ((uint32_t*)g_kf)[((size_t)row * KW + col) >> 1] = hsplit_hi(ox0, oy0);
                    ((uint32_t*)g_kf)[((size_t)(row + 8) * KW + col) >> 1] = hsplit_hi(ox1, oy1);
                }
            } else {
                int col = n0 - 5120 + coll;
                ((uint32_t*)g_vf)[((size_t)row * KW + col) >> 1] = hsplit_hi(v0, v1);
                ((uint32_t*)g_vf)[((size_t)(row + 8) * KW + col) >> 1] = hsplit_hi(v2, v3);
            }
        }
    }
}

// gemm_wo: output projection (A = O single fp16 in g_xf), fp32 C out.
__global__ __launch_bounds__(512, 1)
void gemm_wo(float* __restrict__ C)
{
    extern __shared__ char smc[];
    const uint32_t sb = smem_u32(smc);
    const int tid  = threadIdx.x;
    const int lane = tid & 31;
    const int wid  = tid >> 5;
    const int warp_m = wid >> 2;
    const int warp_n = wid & 3;
    const int m0 = blockIdx.y * 256;
    const int n0 = blockIdx.x * 128;
    const int K = QW;
    const int NT = K >> 6;
    const int N = DIM;

    const __half* Bp = g_wo + (size_t)n0 * K;
    GEMM1_PROLOGUE(g_xf, Bp)
    GEMM1_LOOP()

#pragma unroll
    for (int mt = 0; mt < 4; mt++) {
        int row = m0 + warp_m * 64 + mt * 16 + (lane >> 2);
#pragma unroll
        for (int nt = 0; nt < 4; nt++) {
            int col = n0 + warp_n * 32 + nt * 8 + (lane & 3) * 2;
            *(float2*)(C + (size_t)row * N + col) =
                make_float2(acc[mt][nt][0], acc[mt][nt][1]);
            *(float2*)(C + (size_t)(row + 8) * N + col) =
                make_float2(acc[mt][nt][2], acc[mt][nt][3]);
        }
    }
}

// ---------------------------------------------------------------------------
// flash_mma2: causal attention, all single fp16, Q pre-scaled.
// Br=128, Bc=128 (halved tile-iteration overhead), 8 warps.
// Diagonal tile: per-warp group skipping for both S (g4>w) and PV (kk>w).
// smem: Q 0..34815 | stage s at 34816+s*69632 {K 0, V +34816}. Pitch 272B.
// Total 174080 B.
// ---------------------------------------------------------------------------
#define FA6_SMEM 174080

__global__ __launch_bounds__(256, 1)
void flash_mma2()
{
    extern __shared__ char sm2[];
    const uint32_t sb = smem_u32(sm2);
    const int qb = (int)gridDim.x - 1 - (int)blockIdx.x;   // heavy blocks first
    const int h = blockIdx.y, b = blockIdx.z;
    const int kvh = h >> 2;
    const int tid = threadIdx.x, lane = tid & 31, w = tid >> 5;
    const uint32_t oKV0 = 34816u, KVST = 69632u;

    // ---- Q tile (128 rows x 128 cols) via cp.async ----
    {
        const size_t qrb = (size_t)(b * SEQ + qb * 128) * QW + h * HD;
#pragma unroll
        for (int j = 0; j < 8; j++) {
            int g = tid + 256 * j;
            int row = g >> 4, c16 = g & 15;
            const __half* src = g_qf + qrb + (size_t)row * QW + c16 * 8;
            CP_ASYNC16(sb + (uint32_t)row * 272u + (uint32_t)c16 * 16u, src);
        }
    }

#define ISSUE_KV(kb_) do { \
        const size_t rb_ = (size_t)(b * SEQ + (kb_) * 128) * KW + kvh * HD; \
        const uint32_t st_ = sb + oKV0 + (uint32_t)((kb_) & 1) * KVST; \
        _Pragma("unroll") \
        for (int j = 0; j < 16; j++) { \
            int g = tid + 256 * j; \
            int buf = g >> 11, idx = g & 2047; \
            int row = idx >> 4, c16 = idx & 15; \
            const __half* src = (buf ? g_vf : g_kf) + rb_ + (size_t)row * KW + c16 * 8; \
            CP_ASYNC16(st_ + (uint32_t)buf * 34816u + (uint32_t)row * 272u + (uint32_t)c16 * 16u, src); \
        } \
        CP_COMMIT(); \
    } while (0)

    ISSUE_KV(0);   // commits Q loads too

    float acc_o[16][4];
#pragma unroll
    for (int n = 0; n < 16; n++)
#pragma unroll
        for (int d = 0; d < 4; d++) acc_o[n][d] = 0.0f;
    float mA = -CUDART_INF_F, mB = -CUDART_INF_F, lA = 0.0f, lB = 0.0f;

    const int growA = qb * 128 + w * 16 + (lane >> 2);
    const uint32_t qa  = sb + (uint32_t)(w * 16 + (lane & 15)) * 272u + (uint32_t)(lane >> 4) * 16u;
    const uint32_t lrw = (uint32_t)(lane & 15) * 272u + (uint32_t)(lane >> 4) * 16u;

    const int NT = qb + 1;   // 128-wide kv tiles up to & including the diagonal
    for (int kb = 0; kb < NT; kb++) {
        CP_WAIT(0);
        __syncthreads();
        if (kb + 1 < NT) ISSUE_KV(kb + 1);

        const bool diag = (kb == qb);
        const uint32_t kvst = sb + oKV0 + (uint32_t)(kb & 1) * KVST;
        const uint32_t kvb  = kvst + lrw;
        const uint32_t vvb  = kvst + 34816u + lrw;

        // ---- S = Q K^T (skip fully-masked n-groups on the diagonal tile) ----
        float accs[16][4];
#pragma unroll
        for (int n = 0; n < 16; n++)
#pragma unroll
            for (int d = 0; d < 4; d++) accs[n][d] = 0.0f;

#pragma unroll
        for (int k16 = 0; k16 < 8; k16++) {
            const uint32_t ko = (uint32_t)k16 * 32u;
            uint32_t qh[4];
            LDSM4(qh[0], qh[1], qh[2], qh[3], qa + ko);
#pragma unroll
            for (int g4 = 0; g4 < 8; g4++) {
                if (diag && g4 > w) continue;   // warp-uniform skip
                uint32_t ka = kvb + (uint32_t)g4 * (16u * 272u) + ko;
                uint32_t kh[4];
                LDSM4(kh[0], kh[1], kh[2], kh[3], ka);
                MMA16816(accs[g4 * 2],     qh, kh[0], kh[2]);
                MMA16816(accs[g4 * 2 + 1], qh, kh[1], kh[3]);
            }
        }

        // ---- diagonal masking ----
        if (diag) {
#pragma unroll
            for (int nt = 0; nt < 16; nt++) {
                const int g4 = nt >> 1;
                if (g4 > w) {
                    accs[nt][0] = accs[nt][1] = accs[nt][2] = accs[nt][3] = -1e9f;
                } else if (g4 == w) {
                    int col = kb * 128 + nt * 8 + (lane & 3) * 2;
                    if (col     > growA)     accs[nt][0] = -1e9f;
                    if (col + 1 > growA)     accs[nt][1] = -1e9f;
                    if (col     > growA + 8) accs[nt][2] = -1e9f;
                    if (col + 1 > growA + 8) accs[nt][3] = -1e9f;
                }
            }
        }

        // ---- online softmax (quad shuffles) ----
        float mrA = -CUDART_INF_F, mrB = -CUDART_INF_F;
#pragma unroll
        for (int nt = 0; nt < 16; nt++) {
            mrA = fmaxf(mrA, fmaxf(accs[nt][0], accs[nt][1]));
            mrB = fmaxf(mrB, fmaxf(accs[nt][2], accs[nt][3]));
        }
        mrA = fmaxf(mrA, __shfl_xor_sync(0xffffffffu, mrA, 1));
        mrA = fmaxf(mrA, __shfl_xor_sync(0xffffffffu, mrA, 2));
        mrB = fmaxf(mrB, __shfl_xor_sync(0xffffffffu, mrB, 1));
        mrB = fmaxf(mrB, __shfl_xor_sync(0xffffffffu, mrB, 2));
        float mnA = fmaxf(mA, mrA), mnB = fmaxf(mB, mrB);
        float corrA = __expf(mA - mnA), corrB = __expf(mB - mnB);
        mA = mnA; mB = mnB;

        float sumA = 0.0f, sumB = 0.0f;
#pragma unroll
        for (int nt = 0; nt < 16; nt++) {
            float p0 = __expf(accs[nt][0] - mnA);
            float p1 = __expf(accs[nt][1] - mnA);
            float p2 = __expf(accs[nt][2] - mnB);
            float p3 = __expf(accs[nt][3] - mnB);
            sumA += p0 + p1; sumB += p2 + p3;
            accs[nt][0] = p0; accs[nt][1] = p1; accs[nt][2] = p2; accs[nt][3] = p3;
        }
        sumA += __shfl_xor_sync(0xffffffffu, sumA, 1);
        sumA += __shfl_xor_sync(0xffffffffu, sumA, 2);
        sumB += __shfl_xor_sync(0xffffffffu, sumB, 1);
        sumB += __shfl_xor_sync(0xffffffffu, sumB, 2);
        lA = lA * corrA + sumA;
        lB = lB * corrB + sumB;

        // ---- rescale O ----
#pragma unroll
        for (int nt = 0; nt < 16; nt++) {
            acc_o[nt][0] *= corrA; acc_o[nt][1] *= corrA;
            acc_o[nt][2] *= corrB; acc_o[nt][3] *= corrB;
        }

        // ---- O += P V (skip all-zero P groups on the diagonal tile) ----
#pragma unroll
        for (int kk = 0; kk < 8; kk++) {
            if (diag && kk > w) continue;   // P == 0 there
            uint32_t aH[4];
            aH[0] = hsplit_hi(accs[2*kk][0],   accs[2*kk][1]);
            aH[1] = hsplit_hi(accs[2*kk][2],   accs[2*kk][3]);
            aH[2] = hsplit_hi(accs[2*kk+1][0], accs[2*kk+1][1]);
            aH[3] = hsplit_hi(accs[2*kk+1][2], accs[2*kk+1][3]);
#pragma unroll
            for (int g = 0; g < 8; g++) {
                uint32_t va = vvb + (uint32_t)kk * (16u * 272u) + (uint32_t)g * 32u;
                uint32_t vh[4];
                LDSM4T(vh[0], vh[1], vh[2], vh[3], va);
                MMA16816(acc_o[2*g],   aH, vh[0], vh[1]);
                MMA16816(acc_o[2*g+1], aH, vh[2], vh[3]);
            }
        }
    }

    // ---- epilogue: O/l -> single fp16 into g_xf ----
    {
        float invA = 1.0f / lA, invB = 1.0f / lB;
        uint32_t* of32 = (uint32_t*)g_xf;
        size_t rowA = (size_t)(b * SEQ + qb * 128 + w * 16 + (lane >> 2));
#pragma unroll
        for (int nt = 0; nt < 16; nt++) {
            int col = h * HD + nt * 8 + (lane & 3) * 2;
            of32[(rowA * QW + col) >> 1] =
                hsplit_hi(acc_o[nt][0] * invA, acc_o[nt][1] * invA);
            of32[((rowA + 8) * QW + col) >> 1] =
                hsplit_hi(acc_o[nt][2] * invB, acc_o[nt][3] * invB);
        }
    }
#undef ISSUE_KV
}

// ---------------------------------------------------------------------------
// Launch
// ---------------------------------------------------------------------------
extern "C" void kernel_launch(void* const* d_in, const int* in_sizes, int n_in,
                              void* d_out, int out_size)
{
    const float* x  = (const float*)d_in[0];
    const float* wq = (const float*)d_in[1];
    const float* wk = (const float*)d_in[2];
    const float* wv = (const float*)d_in[3];
    const float* wo = (const float*)d_in[4];
    const float* fc = (const float*)d_in[7];
    const float* fs = (const float*)d_in[8];
    float* out = (float*)d_out;

    __half *pxf, *pwq, *pwk, *pwv, *pwo;
    cudaGetSymbolAddress((void**)&pxf, g_xf);
    cudaGetSymbolAddress((void**)&pwq, g_wq);
    cudaGetSymbolAddress((void**)&pwk, g_wk);
    cudaGetSymbolAddress((void**)&pwv, g_wv);
    cudaGetSymbolAddress((void**)&pwo, g_wo);

    cudaFuncSetAttribute(gemm_qkv, cudaFuncAttributeMaxDynamicSharedMemorySize, (int)G1SMEM);
    cudaFuncSetAttribute(gemm_wo, cudaFuncAttributeMaxDynamicSharedMemorySize, (int)G1SMEM);
    cudaFuncSetAttribute(flash_mma2, cudaFuncAttributeMaxDynamicSharedMemorySize, FA6_SMEM);

    // convert x to single fp16, transpose weights (single fp16)
    convert_half<<<(MROWS * DIM / 4 + 255) / 256, 256>>>(x, pxf, MROWS * DIM / 4);
    transpose_half<<<dim3(QW / 32, DIM / 32), dim3(32, 8)>>>(wq, pwq, DIM, QW);
    transpose_half<<<dim3(KW / 32, DIM / 32), dim3(32, 8)>>>(wk, pwk, DIM, KW);
    transpose_half<<<dim3(KW / 32, DIM / 32), dim3(32, 8)>>>(wv, pwv, DIM, KW);
    transpose_half<<<dim3(DIM / 32, QW / 32), dim3(32, 8)>>>(wo, pwo, QW, DIM);

    // fused QKV projection (x single) + RoPE epilogue — 256x128 tiles
    gemm_qkv<<<dim3(6144 / 128, MROWS / 256), 512, G1SMEM>>>(fc, fs);

    // flash attention (Bc=128, diag skipping; O single fp16 into g_xf)
    flash_mma2<<<dim3(SEQ / 128, NH, BSZ), 256, FA6_SMEM>>>();

    // output projection (single x single) — 256x128 tiles
    gemm_wo<<<dim3(DIM / 128, MROWS / 256), 512, G1SMEM>>>(out);
}

// round 16
// speedup vs baseline: 1.0493x; 1.0493x over previous
#include <cuda_runtime.h>
#include <cuda_fp16.h>
#include <math_constants.h>
#include <cstdint>

#define BSZ   2
#define SEQ   2048
#define DIM   4096
#define NH    32
#define NKV   8
#define HD    128
#define MROWS (BSZ*SEQ)   /* 4096 */
#define QW    (NH*HD)     /* 4096 */
#define KW    (NKV*HD)    /* 1024 */

// ---------------------------------------------------------------------------
// Static device scratch
// ---------------------------------------------------------------------------
__device__ __half g_xf[(size_t)MROWS * DIM];  // x single fp16 -> later O single fp16
__device__ __half g_qf[(size_t)MROWS * QW];   // Q post-RoPE (pre-scaled by 1/sqrt(d))
__device__ __half g_kf[(size_t)MROWS * KW];   // K post-RoPE, single fp16
__device__ __half g_vf[(size_t)MROWS * KW];   // V, single fp16
__device__ __half g_wq[(size_t)QW * DIM];     // transposed weights, single fp16
__device__ __half g_wk[(size_t)KW * DIM];
__device__ __half g_wv[(size_t)KW * DIM];
__device__ __half g_wo[(size_t)DIM * QW];

// ---------------------------------------------------------------------------
// PTX helpers
// ---------------------------------------------------------------------------
__device__ __forceinline__ uint32_t smem_u32(const void* p) {
    uint32_t a;
    asm("{ .reg .u64 t; cvta.to.shared.u64 t, %1; cvt.u32.u64 %0, t; }" : "=r"(a) : "l"(p));
    return a;
}
#define CP_ASYNC16(dst, src) \
    asm volatile("cp.async.cg.shared.global [%0], [%1], 16;" :: "r"(dst), "l"(src))
#define CP_COMMIT() asm volatile("cp.async.commit_group;" ::: "memory")
#define CP_WAIT(n)  asm volatile("cp.async.wait_group %0;" :: "n"(n) : "memory")

#define LDSM4(R0, R1, R2, R3, addr) \
    asm volatile("ldmatrix.sync.aligned.m8n8.x4.shared.b16 {%0,%1,%2,%3}, [%4];" \
        : "=r"(R0), "=r"(R1), "=r"(R2), "=r"(R3) : "r"(addr))
#define LDSM4T(R0, R1, R2, R3, addr) \
    asm volatile("ldmatrix.sync.aligned.m8n8.x4.trans.shared.b16 {%0,%1,%2,%3}, [%4];" \
        : "=r"(R0), "=r"(R1), "=r"(R2), "=r"(R3) : "r"(addr))

#define MMA16816(D, A, B0, B1) \
    asm volatile("mma.sync.aligned.m16n8k16.row.col.f32.f16.f16.f32 " \
        "{%0,%1,%2,%3},{%4,%5,%6,%7},{%8,%9},{%0,%1,%2,%3};" \
        : "+f"((D)[0]), "+f"((D)[1]), "+f"((D)[2]), "+f"((D)[3]) \
        : "r"((A)[0]), "r"((A)[1]), "r"((A)[2]), "r"((A)[3]), "r"(B0), "r"(B1))

__device__ __forceinline__ uint32_t pack_h(__half a, __half b) {
    union { __half h[2]; uint32_t u; } t;
    t.h[0] = a; t.h[1] = b;
    return t.u;
}
__device__ __forceinline__ uint32_t hsplit_hi(float a, float b) {
    return pack_h(__float2half_rn(a), __float2half_rn(b));
}

// ---------------------------------------------------------------------------
// convert_half: fp32 -> fp16 single
// ---------------------------------------------------------------------------
__global__ void convert_half(const float* __restrict__ in,
                             __half* __restrict__ o, int n4)
{
    int i = blockIdx.x * blockDim.x + threadIdx.x;
    if (i >= n4) return;
    float4 v = ((const float4*)in)[i];
    uint2 H;
    H.x = hsplit_hi(v.x, v.y); H.y = hsplit_hi(v.z, v.w);
    ((uint2*)o)[i] = H;
}

// ---------------------------------------------------------------------------
// transpose_half: fp32 [R,C] -> fp16 [C,R] single
// ---------------------------------------------------------------------------
__global__ void transpose_half(const float* __restrict__ in,
                               __half* __restrict__ o, int R, int C)
{
    __shared__ float t[32][33];
    int c0 = blockIdx.x * 32, r0 = blockIdx.y * 32;
    int tx = threadIdx.x, ty = threadIdx.y;
#pragma unroll
    for (int i = 0; i < 4; i++)
        t[ty + 8 * i][tx] = in[(size_t)(r0 + ty + 8 * i) * C + c0 + tx];
    __syncthreads();
#pragma unroll
    for (int i = 0; i < 4; i++)
        o[(size_t)(c0 + ty + 8 * i) * R + r0 + tx] = __float2half_rn(t[tx][ty + 8 * i]);
}

// ===========================================================================
// 1-term GEMM machinery (unchanged — at the HMMA ceiling).
// 256x128 block tile, BK=64, 512 threads (16 warps 4x4), 4 stages.
// ===========================================================================
#define G1STG  55296u
#define G1SMEM (4u * G1STG)

#define GEMM1_PROLOGUE(AP, BP) \
    uint32_t dstoff[6]; \
    const __half* srcrow[6]; \
    _Pragma("unroll") \
    for (int j = 0; j < 6; j++) { \
        int c   = tid + 512 * j; \
        int bufB = (c >= 2048); \
        int idx = bufB ? (c - 2048) : c; \
        int row = idx >> 3; \
        int kc  = idx & 7; \
        dstoff[j] = (uint32_t)bufB * 36864u + (uint32_t)row * 144u + (uint32_t)kc * 16u; \
        const __half* base = bufB ? (BP) + (size_t)row * K \
                                  : (AP) + (size_t)(m0 + row) * K; \
        srcrow[j] = base + kc * 8; \
    }

#define ISSUE1(kt) do { \
        uint32_t stb = sb + (uint32_t)((kt) & 3) * G1STG; \
        const int kel = (kt) << 6; \
        _Pragma("unroll") \
        for (int j = 0; j < 6; j++) \
            CP_ASYNC16(stb + dstoff[j], srcrow[j] + kel); \
        CP_COMMIT(); \
    } while (0)

#define GEMM1_LOOP() \
    float acc[4][4][4]; \
    _Pragma("unroll") \
    for (int a = 0; a < 4; a++) \
        _Pragma("unroll") \
        for (int b2 = 0; b2 < 4; b2++) \
            _Pragma("unroll") \
            for (int d = 0; d < 4; d++) acc[a][b2][d] = 0.0f; \
    ISSUE1(0); \
    ISSUE1(1); \
    ISSUE1(2); \
    const uint32_t a_lrow = (uint32_t)(warp_m * 64 + (lane & 15)) * 144u + (uint32_t)(lane >> 4) * 16u; \
    const uint32_t b_lrow = 36864u + (uint32_t)(warp_n * 32 + (lane & 15)) * 144u + (uint32_t)(lane >> 4) * 16u; \
    for (int kt = 0; kt < NT; kt++) { \
        if (kt + 2 < NT)      { CP_WAIT(2); } \
        else if (kt + 1 < NT) { CP_WAIT(1); } \
        else                  { CP_WAIT(0); } \
        __syncthreads(); \
        if (kt + 3 < NT) ISSUE1(kt + 3); \
        const uint32_t stb = sb + (uint32_t)(kt & 3) * G1STG; \
        _Pragma("unroll") \
        for (int k16 = 0; k16 < 4; k16++) { \
            const uint32_t koff = (uint32_t)k16 * 32u; \
            uint32_t ah[4][4]; \
            _Pragma("unroll") \
            for (int mt = 0; mt < 4; mt++) { \
                uint32_t addr = stb + a_lrow + (uint32_t)mt * (16u * 144u) + koff; \
                LDSM4(ah[mt][0], ah[mt][1], ah[mt][2], ah[mt][3], addr); \
            } \
            uint32_t bh[2][4]; \
            _Pragma("unroll") \
            for (int bt = 0; bt < 2; bt++) { \
                uint32_t addr = stb + b_lrow + (uint32_t)bt * (16u * 144u) + koff; \
                LDSM4(bh[bt][0], bh[bt][1], bh[bt][2], bh[bt][3], addr); \
            } \
            _Pragma("unroll") \
            for (int mt = 0; mt < 4; mt++) { \
                _Pragma("unroll") \
                for (int nt = 0; nt < 4; nt++) { \
                    const int bt = nt >> 1, hf = nt & 1; \
                    MMA16816(acc[mt][nt], ah[mt], bh[bt][hf], bh[bt][hf + 2]); \
                } \
            } \
        } \
    }

// gemm_qkv: fused QKV projection with RoPE epilogue (Q pre-scaled by 1/sqrt d).
__global__ __launch_bounds__(512, 1)
void gemm_qkv(const float* __restrict__ fc, const float* __restrict__ fs)
{
    extern __shared__ char smc[];
    const uint32_t sb = smem_u32(smc);
    const int tid  = threadIdx.x;
    const int lane = tid & 31;
    const int wid  = tid >> 5;
    const int warp_m = wid >> 2;
    const int warp_n = wid & 3;
    const int m0 = blockIdx.y * 256;
    const int n0 = blockIdx.x * 128;
    const int K = DIM;
    const int NT = K >> 6;
    const float SC = 0.08838834764831845f;

    const __half* Bp;
    if (n0 < 4096)      Bp = g_wq + (size_t)n0 * K;
    else if (n0 < 5120) Bp = g_wk + (size_t)(n0 - 4096) * K;
    else                Bp = g_wv + (size_t)(n0 - 5120) * K;

    GEMM1_PROLOGUE(g_xf, Bp)
    GEMM1_LOOP()

#pragma unroll
    for (int mt = 0; mt < 4; mt++) {
        int row = m0 + warp_m * 64 + mt * 16 + (lane >> 2);
        int s0 = row & (SEQ - 1);
        int s1 = (row + 8) & (SEQ - 1);
#pragma unroll
        for (int nt = 0; nt < 4; nt++) {
            int coll = warp_n * 32 + nt * 8 + (lane & 3) * 2;
            float v0 = acc[mt][nt][0], v1 = acc[mt][nt][1];
            float v2 = acc[mt][nt][2], v3 = acc[mt][nt][3];
            if (n0 < 5120) {
                int col = (n0 < 4096) ? (n0 + coll) : (n0 - 4096 + coll);
                int i = (col & (HD - 1)) >> 1;
                float c0 = fc[s0 * 64 + i], sn0 = fs[s0 * 64 + i];
                float c1 = fc[s1 * 64 + i], sn1 = fs[s1 * 64 + i];
                float ox0 = v0 * c0 - v1 * sn0, oy0 = v0 * sn0 + v1 * c0;
                float ox1 = v2 * c1 - v3 * sn1, oy1 = v2 * sn1 + v3 * c1;
                if (n0 < 4096) {
                    ((uint32_t*)g_qf)[((size_t)row * QW + col) >> 1] =
                        hsplit_hi(ox0 * SC, oy0 * SC);
                    ((uint32_t*)g_qf)[((size_t)(row + 8) * QW + col) >> 1] =
                        hsplit_hi(ox1 * SC, oy1 * SC);
                } else {
                    ((uint32_t*)g_kf)[((size_t)row * KW + col) >> 1] = hsplit_hi(ox0, oy0);
                    ((uint32_t*)g_kf)[((size_t)(row + 8) * KW + col) >> 1] = hsplit_hi(ox1, oy1);
                }
            } else {
                int col = n0 - 5120 + coll;
                ((uint32_t*)g_vf)[((size_t)row * KW + col) >> 1] = hsplit_hi(v0, v1);
                ((uint32_t*)g_vf)[((size_t)(row + 8) * KW + col) >> 1] = hsplit_hi(v2, v3);
            }
        }
    }
}

// gemm_wo: output projection (A = O single fp16 in g_xf), fp32 C out.
__global__ __launch_bounds__(512, 1)
void gemm_wo(float* __restrict__ C)
{
    extern __shared__ char smc[];
    const uint32_t sb = smem_u32(smc);
    const int tid  = threadIdx.x;
    const int lane = tid & 31;
    const int wid  = tid >> 5;
    const int warp_m = wid >> 2;
    const int warp_n = wid & 3;
    const int m0 = blockIdx.y * 256;
    const int n0 = blockIdx.x * 128;
    const int K = QW;
    const int NT = K >> 6;
    const int N = DIM;

    const __half* Bp = g_wo + (size_t)n0 * K;
    GEMM1_PROLOGUE(g_xf, Bp)
    GEMM1_LOOP()

#pragma unroll
    for (int mt = 0; mt < 4; mt++) {
        int row = m0 + warp_m * 64 + mt * 16 + (lane >> 2);
#pragma unroll
        for (int nt = 0; nt < 4; nt++) {
            int col = n0 + warp_n * 32 + nt * 8 + (lane & 3) * 2;
            *(float2*)(C + (size_t)row * N + col) =
                make_float2(acc[mt][nt][0], acc[mt][nt][1]);
            *(float2*)(C + (size_t)(row + 8) * N + col) =
                make_float2(acc[mt][nt][2], acc[mt][nt][3]);
        }
    }
}

// ---------------------------------------------------------------------------
// flash_mma2: R13-exact structure (Br=128, Bc=64, all single fp16, Q
// pre-scaled) with a 3-deep KV ring (slot kb%3; slot (kb+2)%3 = (kb-1)%3 is
// written only after the barrier where all warps finished reading kb-1).
// smem: Q 0..34815 | stage s at 34816+s*34816 {K 0, V +17408}. Total 139264 B.
// ---------------------------------------------------------------------------
#define FA7_SMEM 139264

__global__ __launch_bounds__(256, 1)
void flash_mma2()
{
    extern __shared__ char sm2[];
    const uint32_t sb = smem_u32(sm2);
    const int qb = (int)gridDim.x - 1 - (int)blockIdx.x;   // heavy blocks first
    const int h = blockIdx.y, b = blockIdx.z;
    const int kvh = h >> 2;
    const int tid = threadIdx.x, lane = tid & 31, w = tid >> 5;
    const uint32_t oKV0 = 34816u, KVST = 34816u;

    // ---- Q tile (128 rows x 128 cols, single fp16) via cp.async ----
    {
        const size_t qrb = (size_t)(b * SEQ + qb * 128) * QW + h * HD;
#pragma unroll
        for (int j = 0; j < 8; j++) {
            int g = tid + 256 * j;
            int row = g >> 4, c16 = g & 15;
            const __half* src = g_qf + qrb + (size_t)row * QW + c16 * 8;
            CP_ASYNC16(sb + (uint32_t)row * 272u + (uint32_t)c16 * 16u, src);
        }
    }

#define ISSUE_KV(kb_) do { \
        const size_t rb_ = (size_t)(b * SEQ + (kb_) * 64) * KW + kvh * HD; \
        const uint32_t st_ = sb + oKV0 + (uint32_t)((kb_) % 3) * KVST; \
        _Pragma("unroll") \
        for (int j = 0; j < 8; j++) { \
            int g = tid + 256 * j; \
            int buf = g >> 10, idx = g & 1023; \
            int row = idx >> 4, c16 = idx & 15; \
            const __half* src = (buf ? g_vf : g_kf) + rb_ + (size_t)row * KW + c16 * 8; \
            CP_ASYNC16(st_ + (uint32_t)buf * 17408u + (uint32_t)row * 272u + (uint32_t)c16 * 16u, src); \
        } \
        CP_COMMIT(); \
    } while (0)

    const int NT = 2 * qb + 2;
    ISSUE_KV(0);                     // commits Q loads too
    if (1 < NT) ISSUE_KV(1);

    float acc_o[16][4];
#pragma unroll
    for (int n = 0; n < 16; n++)
#pragma unroll
        for (int d = 0; d < 4; d++) acc_o[n][d] = 0.0f;
    float mA = -CUDART_INF_F, mB = -CUDART_INF_F, lA = 0.0f, lB = 0.0f;

    const int growA = qb * 128 + w * 16 + (lane >> 2);
    const uint32_t qa  = sb + (uint32_t)(w * 16 + (lane & 15)) * 272u + (uint32_t)(lane >> 4) * 16u;
    const uint32_t lrw = (uint32_t)(lane & 15) * 272u + (uint32_t)(lane >> 4) * 16u;

    for (int kb = 0; kb < NT; kb++) {
        if (kb + 1 < NT) { CP_WAIT(1); } else { CP_WAIT(0); }
        __syncthreads();
        if (kb + 2 < NT) ISSUE_KV(kb + 2);

        if (kb * 64 > qb * 128 + w * 16 + 15) continue;   // fully masked for this warp

        const uint32_t kvst = sb + oKV0 + (uint32_t)(kb % 3) * KVST;
        const uint32_t kvb  = kvst + lrw;
        const uint32_t vvb  = kvst + 17408u + lrw;

        // ---- S = Q K^T (Q pre-scaled) ----
        float accs[8][4];
#pragma unroll
        for (int n = 0; n < 8; n++)
#pragma unroll
            for (int d = 0; d < 4; d++) accs[n][d] = 0.0f;

#pragma unroll
        for (int k16 = 0; k16 < 8; k16++) {
            const uint32_t ko = (uint32_t)k16 * 32u;
            uint32_t qh[4];
            LDSM4(qh[0], qh[1], qh[2], qh[3], qa + ko);
#pragma unroll
            for (int g4 = 0; g4 < 4; g4++) {
                uint32_t ka = kvb + (uint32_t)g4 * (16u * 272u) + ko;
                uint32_t kh[4];
                LDSM4(kh[0], kh[1], kh[2], kh[3], ka);
                MMA16816(accs[g4 * 2],     qh, kh[0], kh[2]);
                MMA16816(accs[g4 * 2 + 1], qh, kh[1], kh[3]);
            }
        }

        // ---- causal mask (scale folded into Q) ----
        const bool need_mask = (kb * 64 + 63 > qb * 128 + w * 16);
        if (need_mask) {
#pragma unroll
            for (int nt = 0; nt < 8; nt++) {
                int col = kb * 64 + nt * 8 + (lane & 3) * 2;
                if (col     > growA)     accs[nt][0] = -1e9f;
                if (col + 1 > growA)     accs[nt][1] = -1e9f;
                if (col     > growA + 8) accs[nt][2] = -1e9f;
                if (col + 1 > growA + 8) accs[nt][3] = -1e9f;
            }
        }

        // ---- online softmax (quad shuffles) ----
        float mrA = -CUDART_INF_F, mrB = -CUDART_INF_F;
#pragma unroll
        for (int nt = 0; nt < 8; nt++) {
            mrA = fmaxf(mrA, fmaxf(accs[nt][0], accs[nt][1]));
            mrB = fmaxf(mrB, fmaxf(accs[nt][2], accs[nt][3]));
        }
        mrA = fmaxf(mrA, __shfl_xor_sync(0xffffffffu, mrA, 1));
        mrA = fmaxf(mrA, __shfl_xor_sync(0xffffffffu, mrA, 2));
        mrB = fmaxf(mrB, __shfl_xor_sync(0xffffffffu, mrB, 1));
        mrB = fmaxf(mrB, __shfl_xor_sync(0xffffffffu, mrB, 2));
        float mnA = fmaxf(mA, mrA), mnB = fmaxf(mB, mrB);
        float corrA = __expf(mA - mnA), corrB = __expf(mB - mnB);
        mA = mnA; mB = mnB;

        float sumA = 0.0f, sumB = 0.0f;
#pragma unroll
        for (int nt = 0; nt < 8; nt++) {
            float p0 = __expf(accs[nt][0] - mnA);
            float p1 = __expf(accs[nt][1] - mnA);
            float p2 = __expf(accs[nt][2] - mnB);
            float p3 = __expf(accs[nt][3] - mnB);
            sumA += p0 + p1; sumB += p2 + p3;
            accs[nt][0] = p0; accs[nt][1] = p1; accs[nt][2] = p2; accs[nt][3] = p3;
        }
        sumA += __shfl_xor_sync(0xffffffffu, sumA, 1);
        sumA += __shfl_xor_sync(0xffffffffu, sumA, 2);
        sumB += __shfl_xor_sync(0xffffffffu, sumB, 1);
        sumB += __shfl_xor_sync(0xffffffffu, sumB, 2);
        lA = lA * corrA + sumA;
        lB = lB * corrB + sumB;

        // ---- rescale O ----
#pragma unroll
        for (int nt = 0; nt < 16; nt++) {
            acc_o[nt][0] *= corrA; acc_o[nt][1] *= corrA;
            acc_o[nt][2] *= corrB; acc_o[nt][3] *= corrB;
        }

        // ---- O += P V ----
#pragma unroll
        for (int kk = 0; kk < 4; kk++) {
            uint32_t aH[4];
            aH[0] = hsplit_hi(accs[2*kk][0],   accs[2*kk][1]);
            aH[1] = hsplit_hi(accs[2*kk][2],   accs[2*kk][3]);
            aH[2] = hsplit_hi(accs[2*kk+1][0], accs[2*kk+1][1]);
            aH[3] = hsplit_hi(accs[2*kk+1][2], accs[2*kk+1][3]);
#pragma unroll
            for (int g = 0; g < 8; g++) {
                uint32_t va = vvb + (uint32_t)kk * (16u * 272u) + (uint32_t)g * 32u;
                uint32_t vh[4];
                LDSM4T(vh[0], vh[1], vh[2], vh[3], va);
                MMA16816(acc_o[2*g],   aH, vh[0], vh[1]);
                MMA16816(acc_o[2*g+1], aH, vh[2], vh[3]);
            }
        }
    }

    // ---- epilogue: O/l -> single fp16 into g_xf ----
    {
        float invA = 1.0f / lA, invB = 1.0f / lB;
        uint32_t* of32 = (uint32_t*)g_xf;
        size_t rowA = (size_t)(b * SEQ + qb * 128 + w * 16 + (lane >> 2));
#pragma unroll
        for (int nt = 0; nt < 16; nt++) {
            int col = h * HD + nt * 8 + (lane & 3) * 2;
            of32[(rowA * QW + col) >> 1] =
                hsplit_hi(acc_o[nt][0] * invA, acc_o[nt][1] * invA);
            of32[((rowA + 8) * QW + col) >> 1] =
                hsplit_hi(acc_o[nt][2] * invB, acc_o[nt][3] * invB);
        }
    }
#undef ISSUE_KV
}

// ---------------------------------------------------------------------------
// Launch
// ---------------------------------------------------------------------------
extern "C" void kernel_launch(void* const* d_in, const int* in_sizes, int n_in,
                              void* d_out, int out_size)
{
    const float* x  = (const float*)d_in[0];
    const float* wq = (const float*)d_in[1];
    const float* wk = (const float*)d_in[2];
    const float* wv = (const float*)d_in[3];
    const float* wo = (const float*)d_in[4];
    const float* fc = (const float*)d_in[7];
    const float* fs = (const float*)d_in[8];
    float* out = (float*)d_out;

    __half *pxf, *pwq, *pwk, *pwv, *pwo;
    cudaGetSymbolAddress((void**)&pxf, g_xf);
    cudaGetSymbolAddress((void**)&pwq, g_wq);
    cudaGetSymbolAddress((void**)&pwk, g_wk);
    cudaGetSymbolAddress((void**)&pwv, g_wv);
    cudaGetSymbolAddress((void**)&pwo, g_wo);

    cudaFuncSetAttribute(gemm_qkv, cudaFuncAttributeMaxDynamicSharedMemorySize, (int)G1SMEM);
    cudaFuncSetAttribute(gemm_wo, cudaFuncAttributeMaxDynamicSharedMemorySize, (int)G1SMEM);
    cudaFuncSetAttribute(flash_mma2, cudaFuncAttributeMaxDynamicSharedMemorySize, FA7_SMEM);

    // convert x to single fp16, transpose weights (single fp16)
    convert_half<<<(MROWS * DIM / 4 + 255) / 256, 256>>>(x, pxf, MROWS * DIM / 4);
    transpose_half<<<dim3(QW / 32, DIM / 32), dim3(32, 8)>>>(wq, pwq, DIM, QW);
    transpose_half<<<dim3(KW / 32, DIM / 32), dim3(32, 8)>>>(wk, pwk, DIM, KW);
    transpose_half<<<dim3(KW / 32, DIM / 32), dim3(32, 8)>>>(wv, pwv, DIM, KW);
    transpose_half<<<dim3(DIM / 32, QW / 32), dim3(32, 8)>>>(wo, pwo, QW, DIM);

    // fused QKV projection (x single) + RoPE epilogue — 256x128 tiles
    gemm_qkv<<<dim3(6144 / 128, MROWS / 256), 512, G1SMEM>>>(fc, fs);

    // flash attention (Bc=64, 3-deep KV ring; O single fp16 into g_xf)
    flash_mma2<<<dim3(SEQ / 128, NH, BSZ), 256, FA7_SMEM>>>();

    // output projection (single x single) — 256x128 tiles
    gemm_wo<<<dim3(DIM / 128, MROWS / 256), 512, G1SMEM>>>(out);
}